// round 14
// baseline (speedup 1.0000x reference)
#include <cuda_runtime.h>

typedef unsigned long long u64;

#define D      192
#define PLANE  (D*D)
#define OUTD   186
#define TX     16
#define TY     32
#define INY    38          // TY + 6
#define SAW    36          // padded raw row width (floats); conflict-free row-major lanes
#define TABW   17          // padded (t01,tsp) row width (ulonglong2)
#define NT     256
#define NBLOCKS 288

// dynamic smem layout (bytes); 4 buffers of each kind
#define RAW_BUF  5472u      // 38*36*4
#define TAB_BUF  10336u     // 38*17*16
#define OFF_A    0u
#define OFF_B    21888u     // 4*RAW_BUF
#define OFF_TAB  43776u
#define SMEM_TOTAL 85120    // 43776 + 4*TAB_BUF

__device__ __forceinline__ u64 pack2(float lo, float hi){
    u64 r; asm("mov.b64 %0,{%1,%2};":"=l"(r):"f"(lo),"f"(hi)); return r;
}
__device__ __forceinline__ void unpack2(u64 v, float& lo, float& hi){
    asm("mov.b64 {%0,%1},%2;":"=f"(lo),"=f"(hi):"l"(v));
}
__device__ __forceinline__ u64 fma2(u64 a,u64 b,u64 c){
    u64 d; asm("fma.rn.f32x2 %0,%1,%2,%3;":"=l"(d):"l"(a),"l"(b),"l"(c)); return d;
}
__device__ __forceinline__ u64 mul2(u64 a,u64 b){
    u64 d; asm("mul.rn.f32x2 %0,%1,%2;":"=l"(d):"l"(a),"l"(b)); return d;
}

// separable Gaussian weights (size 7, sigma 1.5); wz(k)=0 outside [0,6]
#define W0f 0.0366328f
#define W1f 0.1112808f
#define W2f 0.2167453f
#define W3f 0.2706821f
__device__ __forceinline__ float wz(int k){
    if (k < 0 || k > 6) return 0.f;
    return (k==0||k==6)?W0f:(k==1||k==5)?W1f:(k==2||k==4)?W2f:W3f;
}
__device__ __forceinline__ u64 wpz(int a,int b){   // packed weights; folds to constant
    return ((u64)__float_as_uint(wz(b))<<32) | (u64)__float_as_uint(wz(a));
}
__device__ __forceinline__ u64 cpk(float f){        // broadcast constant pair
    return ((u64)__float_as_uint(f)<<32) | (u64)__float_as_uint(f);
}

#define CP_ASYNC16(dst, src) asm volatile("cp.async.cg.shared.global [%0], [%1], 16;" :: "r"(dst), "l"(src))
#define CP_COMMIT() asm volatile("cp.async.commit_group;")
#define CP_WAIT0()  asm volatile("cp.async.wait_group 0;")

__device__ double g_ssim_acc;   // zero-initialized; reset by last block each launch
__device__ int    g_done;

// x-direction conv of a 4-col task; byte offsets precomputed per thread
__device__ __forceinline__ void xconv4(char* SM, unsigned aOff, unsigned bOff, unsigned tOff){
    const float* pa = (const float*)(SM + aOff);
    const float* pb = (const float*)(SM + bOff);
    float a[10], b[10];
    {
        float4 u = *(const float4*)pa;
        float4 v = *(const float4*)(pa+4);
        float2 w = *(const float2*)(pa+8);
        a[0]=u.x;a[1]=u.y;a[2]=u.z;a[3]=u.w;a[4]=v.x;a[5]=v.y;a[6]=v.z;a[7]=v.w;a[8]=w.x;a[9]=w.y;
    }
    {
        float4 u = *(const float4*)pb;
        float4 v = *(const float4*)(pb+4);
        float2 w = *(const float2*)(pb+8);
        b[0]=u.x;b[1]=u.y;b[2]=u.z;b[3]=u.w;b[4]=v.x;b[5]=v.y;b[6]=v.z;b[7]=v.w;b[8]=w.x;b[9]=w.y;
    }
    u64 a01[4], asp[4];
    #pragma unroll
    for (int m=0;m<10;m++){
        u64 pab = pack2(a[m], b[m]);
        float s = fmaf(b[m], b[m], a[m]*a[m]);
        float p = a[m]*b[m];
        u64 psp = pack2(s, p);
        #pragma unroll
        for (int c=0;c<4;c++){
            int k = m-c;
            if (k == 0){ a01[c]=mul2(wpz(0,0),pab); asp[c]=mul2(wpz(0,0),psp); }
            else if (k > 0 && k <= 6){ a01[c]=fma2(wpz(k,k),pab,a01[c]); asp[c]=fma2(wpz(k,k),psp,asp[c]); }
        }
    }
    ulonglong2* tab = (ulonglong2*)(SM + tOff);
    #pragma unroll
    for (int c=0;c<4;c++){
        ulonglong2 s2; s2.x = a01[c]; s2.y = asp[c];
        tab[c] = s2;
    }
}

// y-direction conv, 2 adjacent output rows, from one x-conved slice buffer
__device__ __forceinline__ void ystage(const char* SM, unsigned tabOff,
                                       int r0, int txi,
                                       u64& oa01, u64& oasp, u64& ob01, u64& obsp){
    const ulonglong2* tab = (const ulonglong2*)(SM + tabOff);
    #pragma unroll
    for (int j = 0; j < 8; ++j){
        ulonglong2 f = tab[(r0 + j)*TABW + txi];
        if (j == 0){
            oa01 = mul2(wpz(0,0), f.x);
            oasp = mul2(wpz(0,0), f.y);
        } else {
            if (j < 7){
                oa01 = fma2(wpz(j,j), f.x, oa01);
                oasp = fma2(wpz(j,j), f.y, oasp);
            }
            if (j == 1){
                ob01 = mul2(wpz(0,0), f.x);
                obsp = mul2(wpz(0,0), f.y);
            } else {
                ob01 = fma2(wpz(j-1,j-1), f.x, ob01);
                obsp = fma2(wpz(j-1,j-1), f.y, obsp);
            }
        }
    }
}

// z-conv + packed 2-row SSIM epilogue; B = (sy+1)%7; acc2 packed accumulator
__device__ __forceinline__ void zssim_pair(const u64* Ra01, const u64* Rasp,
                                           const u64* Rb01, const u64* Rbsp,
                                           int B, u64 pmask, u64& acc2){
    u64 m01a = mul2(wpz(0,0), Ra01[B % 7]);
    u64 mspa = mul2(wpz(0,0), Rasp[B % 7]);
    u64 m01b = mul2(wpz(0,0), Rb01[B % 7]);
    u64 mspb = mul2(wpz(0,0), Rbsp[B % 7]);
    #pragma unroll
    for (int k = 1; k < 7; ++k){
        m01a = fma2(wpz(k,k), Ra01[(B + k) % 7], m01a);
        mspa = fma2(wpz(k,k), Rasp[(B + k) % 7], mspa);
        m01b = fma2(wpz(k,k), Rb01[(B + k) % 7], m01b);
        mspb = fma2(wpz(k,k), Rbsp[(B + k) % 7], mspb);
    }
    float mu1a,mu2a,Sa,Pa, mu1b,mu2b,Sb,Pb;
    unpack2(m01a, mu1a, mu2a); unpack2(mspa, Sa, Pa);
    unpack2(m01b, mu1b, mu2b); unpack2(mspb, Sb, Pb);
    u64 pmu1 = pack2(mu1a, mu1b);
    u64 pmu2 = pack2(mu2a, mu2b);
    u64 pS   = pack2(Sa, Sb);
    u64 pP   = pack2(Pa, Pb);

    const u64 K1  = cpk(1.f),  Km1 = cpk(-1.f), K2 = cpk(2.f);
    const u64 Kc1 = cpk(1e-4f), Kc2 = cpk(9e-4f);

    u64 pmm  = mul2(pmu1, pmu2);
    u64 pm1s = mul2(pmu1, pmu1);
    u64 pm2s = mul2(pmu2, pmu2);
    u64 va   = fma2(pmm, K2, Kc1);                    // 2mm + c1
    u64 sP   = fma2(pmm, Km1, pP);                    // P - mm
    u64 vb   = fma2(sP, K2, Kc2);                     // 2(P-mm) + c2
    u64 pnum = mul2(va, vb);
    u64 d1   = fma2(pm2s, K1, fma2(pm1s, K1, Kc1));   // m1s + m2s + c1
    u64 t0   = fma2(pS, K1, Kc2);                     // S + c2
    u64 d2   = fma2(pm2s, Km1, fma2(pm1s, Km1, t0));  // S - m1s - m2s + c2
    u64 pden = mul2(d1, d2);

    float na, nb, da, db;
    unpack2(pnum, na, nb);
    unpack2(pden, da, db);
    float ra = __fdividef(na, da);
    float rb = __fdividef(nb, db);
    acc2 = fma2(pack2(ra, rb), pmask, acc2);
}

__global__ __launch_bounds__(NT,2)
void ssim_main_kernel(const float* __restrict__ X, const float* __restrict__ Y,
                      float* __restrict__ out){
    extern __shared__ char SM[];
    __shared__ float red[NT/32];

    const int t   = threadIdx.x;
    const int txi = t & 15;
    const int q   = t >> 4;

    const int gx0   = blockIdx.x * TX;
    const int gy0   = blockIdx.y * TY;
    const int batch = blockIdx.z >> 1;
    const int chunk = blockIdx.z & 1;

    const float* xb = X + (size_t)batch*PLANE*D + (size_t)(chunk*93)*PLANE;
    const float* yb = Y + (size_t)batch*PLANE*D + (size_t)(chunk*93)*PLANE;

    // ---- cp.async chunk assignment: 2 arrays x 38 rows x 6 chunks = 456 ----
    const float* p1; const float* p2;
    unsigned s1, s2; const bool have2 = (t < 200);
    {
        int cid1 = t;
        int c1   = (cid1 < 228) ? cid1 : cid1 - 228;
        int r1_  = c1/6, ck1 = c1 - 6*r1_;
        int gy1  = min(gy0 + r1_, D-1);
        int gxc1 = gx0 + ck1*4; if (gxc1 + 3 >= D) gxc1 = gx0;
        p1 = ((cid1 < 228) ? xb : yb) + gy1*D + gxc1;
        s1 = (unsigned)__cvta_generic_to_shared(
                 SM + ((cid1 < 228) ? OFF_A : OFF_B) + (unsigned)(r1_*(SAW*4) + ck1*16));
        int cid2 = t + 256;
        int c2   = cid2 - 228;                 // always array b
        int r2_  = c2/6, ck2 = c2 - 6*r2_;
        int gy2  = min(gy0 + r2_, D-1);
        int gxc2 = gx0 + ck2*4; if (gxc2 + 3 >= D) gxc2 = gx0;
        p2 = yb + gy2*D + gxc2;
        s2 = (unsigned)__cvta_generic_to_shared(
                 SM + OFF_B + (unsigned)(r2_*(SAW*4) + ck2*16));
    }

    // ---- x-conv task map: 304 xconv4 units/pair in exactly 10 warp-passes ----
    // Pass 0 (all 256 threads, one task each):
    //   t <  48 : slice 1, ch = t/38 (0 or 1), row = t%38      [s1: ch0 r0-37, ch1 r0-9]
    //   t < 200 : slice 0, u = t-48, ch = u/38, row = u%38      [s0: all 152]
    //   else    : slice 1, u = t-200: u<28 -> (ch1, r10+u) ; else (ch3, r10+u-28)
    // Pass 1 (threads 0-47 only): same slice/row, ch+2 -> rawOff+32, tabOff+128
    //   covers s1: ch2 r0-37, ch3 r0-9.   Total = 304, disjoint, complete.
    // Per-SMSP warp-pass load: {3,3,2,2} (vs R7's {4,2,2,2}).
    unsigned rawOff0, tabOff0; int lim0;
    {
        int sl, ch, row;
        if (t < 48){ sl = 1; ch = t / 38; row = t - 38*ch; }
        else if (t < 200){ int u = t - 48; sl = 0; ch = u / 38; row = u - 38*ch; }
        else { int u = t - 200; sl = 1; ch = (u < 28) ? 1 : 3; row = 10 + ((u < 28) ? u : u - 28); }
        rawOff0 = (unsigned)sl*RAW_BUF + (unsigned)(row*(SAW*4) + ch*16);
        tabOff0 = (unsigned)sl*TAB_BUF + (unsigned)(row*(TABW*16) + ch*64);
        lim0 = sl ? 48 : 49;
    }
    const bool p1act = (t < 48);

    // per-thread z rings (2 output rows x 2 packed fields)
    u64 Ra01[7], Rasp[7], Rb01[7], Rbsp[7];

    const int  r0 = 2*q;
    const bool okx = (gx0 + txi) < OUTD;
    const bool v0  = okx && (gy0 + r0 < OUTD);
    const bool v1  = okx && (gy0 + r0 + 1 < OUTD);
    const u64  pmask = pack2(v0 ? 1.f : 0.f, v1 ? 1.f : 0.f);

    u64 acc2 = 0;   // packed accumulator (0.0f, 0.0f)

    // ---- prologue: slices 0,1 into raw buffers 0,1 (one group) ----
    CP_ASYNC16(s1, p1); if (have2) CP_ASYNC16(s2, p2);
    CP_ASYNC16(s1 + RAW_BUF, p1 + PLANE); if (have2) CP_ASYNC16(s2 + RAW_BUF, p2 + PLANE);
    CP_COMMIT();
    p1 += 2*PLANE; p2 += 2*PLANE;

    unsigned rawRd = 0;    // byte off of raw buffer pair holding slices (2ip, 2ip+1)
    unsigned tabWr = 0;    // byte off of tab buffer pair for x-conv writes

    // pair-iterations ip = 0..50: x-conv slices (2ip,2ip+1), y/z slices (2ip-2,2ip-1)
    for (int pb = 0; pb <= 50; pb += 7){
        #pragma unroll
        for (int pp = 0; pp < 7; ++pp){
            const int ip = pb + pp;
            if (ip > 50) break;

            CP_WAIT0();
            __syncthreads();

            // prefetch slices 2ip+2, 2ip+3 into the opposite raw buffer pair
            {
                unsigned rawW = rawRd ^ (2u*RAW_BUF);
                if (ip <= 48){ CP_ASYNC16(s1 + rawW, p1); if (have2) CP_ASYNC16(s2 + rawW, p2); }
                if (ip <= 47){ CP_ASYNC16(s1 + rawW + RAW_BUF, p1 + PLANE);
                               if (have2) CP_ASYNC16(s2 + rawW + RAW_BUF, p2 + PLANE); }
                CP_COMMIT();
                p1 += 2*PLANE; p2 += 2*PLANE;
            }

            // ---- x-conv of slices 2ip, 2ip+1 (10 balanced warp-passes) ----
            if (ip <= lim0)
                xconv4(SM, OFF_A + rawRd + rawOff0, OFF_B + rawRd + rawOff0,
                           OFF_TAB + tabWr + tabOff0);
            if (p1act && ip <= 48)
                xconv4(SM, OFF_A + rawRd + rawOff0 + 32u, OFF_B + rawRd + rawOff0 + 32u,
                           OFF_TAB + tabWr + tabOff0 + 128u);

            // ---- y/z/SSIM for sy0 = 2ip-2, sy1 = 2ip-1 ----
            if (ip >= 1){
                const unsigned tabRd = tabWr ^ (2u*TAB_BUF);
                const int I0 = (2*pp + 5) % 7;   // sy0 % 7
                const int I1 = (2*pp + 6) % 7;   // sy1 % 7
                const int B0 = (2*pp + 6) % 7;   // (sy0+1) % 7
                const int B1 = (2*pp)     % 7;   // (sy1+1) % 7

                // sy0
                {
                    u64 oa01, oasp, ob01, obsp;
                    ystage(SM, OFF_TAB + tabRd, r0, txi, oa01, oasp, ob01, obsp);
                    Ra01[I0]=oa01; Rasp[I0]=oasp; Rb01[I0]=ob01; Rbsp[I0]=obsp;
                    if (ip >= 4)
                        zssim_pair(Ra01, Rasp, Rb01, Rbsp, B0, pmask, acc2);
                }
                // sy1 (after zssim(sy0): slot I1 still holds sy0-6 until here)
                if (ip <= 49){
                    u64 oa01, oasp, ob01, obsp;
                    ystage(SM, OFF_TAB + tabRd + TAB_BUF, r0, txi, oa01, oasp, ob01, obsp);
                    Ra01[I1]=oa01; Rasp[I1]=oasp; Rb01[I1]=ob01; Rbsp[I1]=obsp;
                    if (ip >= 4)
                        zssim_pair(Ra01, Rasp, Rb01, Rbsp, B1, pmask, acc2);
                }
            }

            rawRd ^= 2u*RAW_BUF;
            tabWr ^= 2u*TAB_BUF;
        }
    }

    // ---- reduction ----
    float alo, ahi; unpack2(acc2, alo, ahi);
    float acc = alo + ahi;
    #pragma unroll
    for (int o = 16; o > 0; o >>= 1)
        acc += __shfl_xor_sync(0xffffffffu, acc, o);
    if ((t & 31) == 0) red[t >> 5] = acc;
    __syncthreads();
    if (t < 32){
        float v = (t < NT/32) ? red[t] : 0.f;
        #pragma unroll
        for (int o = 16; o > 0; o >>= 1)
            v += __shfl_xor_sync(0xffffffffu, v, o);
        if (t == 0){
            atomicAdd(&g_ssim_acc, (double)v);
            __threadfence();
            int old = atomicAdd(&g_done, 1);
            if (old == NBLOCKS - 1){
                __threadfence();
                double total = *((volatile double*)&g_ssim_acc);
                out[0] = (float)(total / 12869712.0);   // 2 * 186^3
                g_ssim_acc = 0.0;                        // reset for next replay
                g_done = 0;
            }
        }
    }
}

extern "C" void kernel_launch(void* const* d_in, const int* in_sizes, int n_in,
                              void* d_out, int out_size){
    const float* x = (const float*)d_in[0];
    const float* y = (const float*)d_in[1];
    float* out = (float*)d_out;

    cudaFuncSetAttribute(ssim_main_kernel,
                         cudaFuncAttributeMaxDynamicSharedMemorySize, SMEM_TOTAL);

    dim3 grid(12, 6, 4);   // 192/16 x-tiles, 192/32 y-tiles, 2 batches * 2 z-chunks
    ssim_main_kernel<<<grid, NT, SMEM_TOTAL>>>(x, y, out);
}

// round 15
// speedup vs baseline: 1.0200x; 1.0200x over previous
#include <cuda_runtime.h>

typedef unsigned long long u64;

#define D      192
#define PLANE  (D*D)
#define OUTD   186
#define TX     16
#define TY     32
#define INY    38          // TY + 6
#define SAW    24          // raw row width (floats), R7 layout
#define TABW   17          // padded (t01,tsp) row width (ulonglong2)
#define NT     256
#define NBLOCKS 288

// dynamic smem layout (bytes); 6 buffers of each kind (two triples)
#define RAW_BUF  3648u      // 38*24*4
#define TAB_BUF  10336u     // 38*17*16
#define RAW_TRI  10944u     // 3*RAW_BUF
#define TAB_TRI  31008u     // 3*TAB_BUF
#define OFF_A    0u
#define OFF_B    21888u     // 6*RAW_BUF
#define OFF_TAB  43776u
#define SMEM_TOTAL 105792   // 43776 + 6*TAB_BUF

__device__ __forceinline__ u64 pack2(float lo, float hi){
    u64 r; asm("mov.b64 %0,{%1,%2};":"=l"(r):"f"(lo),"f"(hi)); return r;
}
__device__ __forceinline__ void unpack2(u64 v, float& lo, float& hi){
    asm("mov.b64 {%0,%1},%2;":"=f"(lo),"=f"(hi):"l"(v));
}
__device__ __forceinline__ u64 fma2(u64 a,u64 b,u64 c){
    u64 d; asm("fma.rn.f32x2 %0,%1,%2,%3;":"=l"(d):"l"(a),"l"(b),"l"(c)); return d;
}
__device__ __forceinline__ u64 mul2(u64 a,u64 b){
    u64 d; asm("mul.rn.f32x2 %0,%1,%2;":"=l"(d):"l"(a),"l"(b)); return d;
}

// separable Gaussian weights (size 7, sigma 1.5); wz(k)=0 outside [0,6]
#define W0f 0.0366328f
#define W1f 0.1112808f
#define W2f 0.2167453f
#define W3f 0.2706821f
__device__ __forceinline__ float wz(int k){
    if (k < 0 || k > 6) return 0.f;
    return (k==0||k==6)?W0f:(k==1||k==5)?W1f:(k==2||k==4)?W2f:W3f;
}
__device__ __forceinline__ u64 wpz(int a,int b){   // packed weights; folds to constant
    return ((u64)__float_as_uint(wz(b))<<32) | (u64)__float_as_uint(wz(a));
}
__device__ __forceinline__ u64 cpk(float f){        // broadcast constant pair
    return ((u64)__float_as_uint(f)<<32) | (u64)__float_as_uint(f);
}

#define CP_ASYNC16(dst, src) asm volatile("cp.async.cg.shared.global [%0], [%1], 16;" :: "r"(dst), "l"(src))
#define CP_COMMIT() asm volatile("cp.async.commit_group;")
#define CP_WAIT0()  asm volatile("cp.async.wait_group 0;")

__device__ double g_ssim_acc;   // zero-initialized; reset by last block each launch
__device__ int    g_done;

// x-direction conv of a 4-col task; byte offsets precomputed per thread
__device__ __forceinline__ void xconv4(char* SM, unsigned aOff, unsigned bOff, unsigned tOff){
    const float* pa = (const float*)(SM + aOff);
    const float* pb = (const float*)(SM + bOff);
    float a[10], b[10];
    {
        float4 u = *(const float4*)pa;
        float4 v = *(const float4*)(pa+4);
        float2 w = *(const float2*)(pa+8);
        a[0]=u.x;a[1]=u.y;a[2]=u.z;a[3]=u.w;a[4]=v.x;a[5]=v.y;a[6]=v.z;a[7]=v.w;a[8]=w.x;a[9]=w.y;
    }
    {
        float4 u = *(const float4*)pb;
        float4 v = *(const float4*)(pb+4);
        float2 w = *(const float2*)(pb+8);
        b[0]=u.x;b[1]=u.y;b[2]=u.z;b[3]=u.w;b[4]=v.x;b[5]=v.y;b[6]=v.z;b[7]=v.w;b[8]=w.x;b[9]=w.y;
    }
    u64 a01[4], asp[4];
    #pragma unroll
    for (int m=0;m<10;m++){
        u64 pab = pack2(a[m], b[m]);
        float s = fmaf(b[m], b[m], a[m]*a[m]);
        float p = a[m]*b[m];
        u64 psp = pack2(s, p);
        #pragma unroll
        for (int c=0;c<4;c++){
            int k = m-c;
            if (k == 0){ a01[c]=mul2(wpz(0,0),pab); asp[c]=mul2(wpz(0,0),psp); }
            else if (k > 0 && k <= 6){ a01[c]=fma2(wpz(k,k),pab,a01[c]); asp[c]=fma2(wpz(k,k),psp,asp[c]); }
        }
    }
    ulonglong2* tab = (ulonglong2*)(SM + tOff);
    #pragma unroll
    for (int c=0;c<4;c++){
        ulonglong2 s2; s2.x = a01[c]; s2.y = asp[c];
        tab[c] = s2;
    }
}

// y-direction conv, 2 adjacent output rows, from one x-conved slice buffer
__device__ __forceinline__ void ystage(const char* SM, unsigned tabOff,
                                       int r0, int txi,
                                       u64& oa01, u64& oasp, u64& ob01, u64& obsp){
    const ulonglong2* tab = (const ulonglong2*)(SM + tabOff);
    #pragma unroll
    for (int j = 0; j < 8; ++j){
        ulonglong2 f = tab[(r0 + j)*TABW + txi];
        if (j == 0){
            oa01 = mul2(wpz(0,0), f.x);
            oasp = mul2(wpz(0,0), f.y);
        } else {
            if (j < 7){
                oa01 = fma2(wpz(j,j), f.x, oa01);
                oasp = fma2(wpz(j,j), f.y, oasp);
            }
            if (j == 1){
                ob01 = mul2(wpz(0,0), f.x);
                obsp = mul2(wpz(0,0), f.y);
            } else {
                ob01 = fma2(wpz(j-1,j-1), f.x, ob01);
                obsp = fma2(wpz(j-1,j-1), f.y, obsp);
            }
        }
    }
}

// z-conv + packed 2-row SSIM epilogue; B = (sy+1)%7; acc2 packed accumulator
__device__ __forceinline__ void zssim_pair(const u64* Ra01, const u64* Rasp,
                                           const u64* Rb01, const u64* Rbsp,
                                           int B, u64 pmask, u64& acc2){
    u64 m01a = mul2(wpz(0,0), Ra01[B % 7]);
    u64 mspa = mul2(wpz(0,0), Rasp[B % 7]);
    u64 m01b = mul2(wpz(0,0), Rb01[B % 7]);
    u64 mspb = mul2(wpz(0,0), Rbsp[B % 7]);
    #pragma unroll
    for (int k = 1; k < 7; ++k){
        m01a = fma2(wpz(k,k), Ra01[(B + k) % 7], m01a);
        mspa = fma2(wpz(k,k), Rasp[(B + k) % 7], mspa);
        m01b = fma2(wpz(k,k), Rb01[(B + k) % 7], m01b);
        mspb = fma2(wpz(k,k), Rbsp[(B + k) % 7], mspb);
    }
    float mu1a,mu2a,Sa,Pa, mu1b,mu2b,Sb,Pb;
    unpack2(m01a, mu1a, mu2a); unpack2(mspa, Sa, Pa);
    unpack2(m01b, mu1b, mu2b); unpack2(mspb, Sb, Pb);
    u64 pmu1 = pack2(mu1a, mu1b);
    u64 pmu2 = pack2(mu2a, mu2b);
    u64 pS   = pack2(Sa, Sb);
    u64 pP   = pack2(Pa, Pb);

    const u64 K1  = cpk(1.f),  Km1 = cpk(-1.f), K2 = cpk(2.f);
    const u64 Kc1 = cpk(1e-4f), Kc2 = cpk(9e-4f);

    u64 pmm  = mul2(pmu1, pmu2);
    u64 pm1s = mul2(pmu1, pmu1);
    u64 pm2s = mul2(pmu2, pmu2);
    u64 va   = fma2(pmm, K2, Kc1);                    // 2mm + c1
    u64 sP   = fma2(pmm, Km1, pP);                    // P - mm
    u64 vb   = fma2(sP, K2, Kc2);                     // 2(P-mm) + c2
    u64 pnum = mul2(va, vb);
    u64 d1   = fma2(pm2s, K1, fma2(pm1s, K1, Kc1));   // m1s + m2s + c1
    u64 t0   = fma2(pS, K1, Kc2);                     // S + c2
    u64 d2   = fma2(pm2s, Km1, fma2(pm1s, Km1, t0));  // S - m1s - m2s + c2
    u64 pden = mul2(d1, d2);

    float na, nb, da, db;
    unpack2(pnum, na, nb);
    unpack2(pden, da, db);
    float ra = __fdividef(na, da);
    float rb = __fdividef(nb, db);
    acc2 = fma2(pack2(ra, rb), pmask, acc2);
}

__global__ __launch_bounds__(NT,2)
void ssim_main_kernel(const float* __restrict__ X, const float* __restrict__ Y,
                      float* __restrict__ out){
    extern __shared__ char SM[];
    __shared__ float red[NT/32];

    const int t   = threadIdx.x;
    const int txi = t & 15;
    const int q   = t >> 4;

    const int gx0   = blockIdx.x * TX;
    const int gy0   = blockIdx.y * TY;
    const int batch = blockIdx.z >> 1;
    const int chunk = blockIdx.z & 1;

    const float* xb = X + (size_t)batch*PLANE*D + (size_t)(chunk*93)*PLANE;
    const float* yb = Y + (size_t)batch*PLANE*D + (size_t)(chunk*93)*PLANE;

    // ---- cp.async chunk assignment: 2 arrays x 38 rows x 6 chunks = 456/slice ----
    const float* p1; const float* p2;
    unsigned s1, s2; const bool have2 = (t < 200);
    {
        int cid1 = t;
        int c1   = (cid1 < 228) ? cid1 : cid1 - 228;
        int r1_  = c1/6, ck1 = c1 - 6*r1_;
        int gy1  = min(gy0 + r1_, D-1);
        int gxc1 = gx0 + ck1*4; if (gxc1 + 3 >= D) gxc1 = gx0;
        p1 = ((cid1 < 228) ? xb : yb) + gy1*D + gxc1;
        s1 = (unsigned)__cvta_generic_to_shared(
                 SM + ((cid1 < 228) ? OFF_A : OFF_B) + (unsigned)(r1_*(SAW*4) + ck1*16));
        int cid2 = t + 256;
        int c2   = cid2 - 228;                 // always array b
        int r2_  = c2/6, ck2 = c2 - 6*r2_;
        int gy2  = min(gy0 + r2_, D-1);
        int gxc2 = gx0 + ck2*4; if (gxc2 + 3 >= D) gxc2 = gx0;
        p2 = yb + gy2*D + gxc2;
        s2 = (unsigned)__cvta_generic_to_shared(
                 SM + OFF_B + (unsigned)(r2_*(SAW*4) + ck2*16));
    }

    // x-conv (R7 map): 152 tasks/slice (38 rows x 4 chunks), threads 0..151,
    // each active thread does the same (row, chunk) for all 3 slices of the triple
    const bool xact = (t < 152);
    const unsigned rawOffX = (unsigned)((t >> 2)*(SAW*4) + (t & 3)*16);
    const unsigned tabOffX = (unsigned)((t >> 2)*(TABW*16) + (t & 3)*64);

    // per-thread z rings (2 output rows x 2 packed fields)
    u64 Ra01[7], Rasp[7], Rb01[7], Rbsp[7];

    const int  r0 = 2*q;
    const bool okx = (gx0 + txi) < OUTD;
    const bool v0  = okx && (gy0 + r0 < OUTD);
    const bool v1  = okx && (gy0 + r0 + 1 < OUTD);
    const u64  pmask = pack2(v0 ? 1.f : 0.f, v1 ? 1.f : 0.f);

    u64 acc2 = 0;   // packed accumulator (0.0f, 0.0f)

    // ---- prologue: slices 0,1,2 into raw buffers 0,1,2 (one group) ----
    #pragma unroll
    for (int k = 0; k < 3; ++k){
        CP_ASYNC16(s1 + (unsigned)k*RAW_BUF, p1 + k*PLANE);
        if (have2) CP_ASYNC16(s2 + (unsigned)k*RAW_BUF, p2 + k*PLANE);
    }
    CP_COMMIT();
    p1 += 3*PLANE; p2 += 3*PLANE;

    unsigned rawRd = 0;    // byte off of raw triple holding slices (3ip..3ip+2)
    unsigned tabWr = 0;    // byte off of tab triple for x-conv writes

    // triple-iterations ip = 0..33: x-conv slices (3ip..3ip+2) [ip<=32],
    // y/z slices (3ip-3..3ip-1) [ip>=1]; 99 slices per chunk, 34 barriers.
    for (int pb = 0; pb <= 33; pb += 7){
        #pragma unroll
        for (int pp = 0; pp < 7; ++pp){
            const int ip = pb + pp;
            if (ip > 33) break;

            CP_WAIT0();
            __syncthreads();

            // prefetch slices 3ip+3..3ip+5 into the opposite raw triple (ip<=31)
            {
                unsigned rawW = rawRd ^ RAW_TRI;
                if (ip <= 31){
                    #pragma unroll
                    for (int k = 0; k < 3; ++k){
                        CP_ASYNC16(s1 + rawW + (unsigned)k*RAW_BUF, p1 + k*PLANE);
                        if (have2) CP_ASYNC16(s2 + rawW + (unsigned)k*RAW_BUF, p2 + k*PLANE);
                    }
                }
                CP_COMMIT();
                p1 += 3*PLANE; p2 += 3*PLANE;
            }

            // ---- x-conv of slices 3ip, 3ip+1, 3ip+2 ----
            if (xact && ip <= 32){
                xconv4(SM, OFF_A + rawRd + rawOffX, OFF_B + rawRd + rawOffX,
                           OFF_TAB + tabWr + tabOffX);
                xconv4(SM, OFF_A + rawRd + RAW_BUF + rawOffX,
                           OFF_B + rawRd + RAW_BUF + rawOffX,
                           OFF_TAB + tabWr + TAB_BUF + tabOffX);
                xconv4(SM, OFF_A + rawRd + 2u*RAW_BUF + rawOffX,
                           OFF_B + rawRd + 2u*RAW_BUF + rawOffX,
                           OFF_TAB + tabWr + 2u*TAB_BUF + tabOffX);
            }

            // ---- y/z/SSIM for sy = 3ip-3, 3ip-2, 3ip-1 ----
            if (ip >= 1){
                const unsigned tabRd = tabWr ^ TAB_TRI;
                const bool zgo = (ip >= 3);      // all three sy >= 6 iff ip >= 3
                // sy0 = 3ip-3 : ring slot (3pp+4)%7, oldest B=(3pp+5)%7
                {
                    const int I = (3*pp + 4) % 7, B = (3*pp + 5) % 7;
                    u64 oa01, oasp, ob01, obsp;
                    ystage(SM, OFF_TAB + tabRd, r0, txi, oa01, oasp, ob01, obsp);
                    Ra01[I]=oa01; Rasp[I]=oasp; Rb01[I]=ob01; Rbsp[I]=obsp;
                    if (zgo) zssim_pair(Ra01, Rasp, Rb01, Rbsp, B, pmask, acc2);
                }
                // sy1 = 3ip-2
                {
                    const int I = (3*pp + 5) % 7, B = (3*pp + 6) % 7;
                    u64 oa01, oasp, ob01, obsp;
                    ystage(SM, OFF_TAB + tabRd + TAB_BUF, r0, txi, oa01, oasp, ob01, obsp);
                    Ra01[I]=oa01; Rasp[I]=oasp; Rb01[I]=ob01; Rbsp[I]=obsp;
                    if (zgo) zssim_pair(Ra01, Rasp, Rb01, Rbsp, B, pmask, acc2);
                }
                // sy2 = 3ip-1
                {
                    const int I = (3*pp + 6) % 7, B = (3*pp) % 7;
                    u64 oa01, oasp, ob01, obsp;
                    ystage(SM, OFF_TAB + tabRd + 2u*TAB_BUF, r0, txi, oa01, oasp, ob01, obsp);
                    Ra01[I]=oa01; Rasp[I]=oasp; Rb01[I]=ob01; Rbsp[I]=obsp;
                    if (zgo) zssim_pair(Ra01, Rasp, Rb01, Rbsp, B, pmask, acc2);
                }
            }

            rawRd ^= RAW_TRI;
            tabWr ^= TAB_TRI;
        }
    }

    // ---- reduction ----
    float alo, ahi; unpack2(acc2, alo, ahi);
    float acc = alo + ahi;
    #pragma unroll
    for (int o = 16; o > 0; o >>= 1)
        acc += __shfl_xor_sync(0xffffffffu, acc, o);
    if ((t & 31) == 0) red[t >> 5] = acc;
    __syncthreads();
    if (t < 32){
        float v = (t < NT/32) ? red[t] : 0.f;
        #pragma unroll
        for (int o = 16; o > 0; o >>= 1)
            v += __shfl_xor_sync(0xffffffffu, v, o);
        if (t == 0){
            atomicAdd(&g_ssim_acc, (double)v);
            __threadfence();
            int old = atomicAdd(&g_done, 1);
            if (old == NBLOCKS - 1){
                __threadfence();
                double total = *((volatile double*)&g_ssim_acc);
                out[0] = (float)(total / 12869712.0);   // 2 * 186^3
                g_ssim_acc = 0.0;                        // reset for next replay
                g_done = 0;
            }
        }
    }
}

extern "C" void kernel_launch(void* const* d_in, const int* in_sizes, int n_in,
                              void* d_out, int out_size){
    const float* x = (const float*)d_in[0];
    const float* y = (const float*)d_in[1];
    float* out = (float*)d_out;

    cudaFuncSetAttribute(ssim_main_kernel,
                         cudaFuncAttributeMaxDynamicSharedMemorySize, SMEM_TOTAL);

    dim3 grid(12, 6, 4);   // 192/16 x-tiles, 192/32 y-tiles, 2 batches * 2 z-chunks
    ssim_main_kernel<<<grid, NT, SMEM_TOTAL>>>(x, y, out);
}

// round 17
// speedup vs baseline: 1.0960x; 1.0745x over previous
#include <cuda_runtime.h>

typedef unsigned long long u64;

#define D      192
#define PLANE  (D*D)
#define OUTD   186
#define TX     16
#define TY     32
#define INY    38          // TY + 6
#define SAW    24          // padded raw row width (floats)
#define TABW   17          // padded (t01,tsp) row width (ulonglong2)
#define NT     256
#define NBLOCKS 288

// dynamic smem layout (bytes); 4 buffers of each kind
#define RAW_BUF  3648u      // 38*24*4
#define TAB_BUF  10336u     // 38*17*16
#define OFF_A    0u
#define OFF_B    14592u     // 4*RAW_BUF
#define OFF_TAB  29184u
#define SMEM_TOTAL 70528    // 29184 + 4*TAB_BUF

__device__ __forceinline__ u64 pack2(float lo, float hi){
    u64 r; asm("mov.b64 %0,{%1,%2};":"=l"(r):"f"(lo),"f"(hi)); return r;
}
__device__ __forceinline__ void unpack2(u64 v, float& lo, float& hi){
    asm("mov.b64 {%0,%1},%2;":"=f"(lo),"=f"(hi):"l"(v));
}
__device__ __forceinline__ u64 fma2(u64 a,u64 b,u64 c){
    u64 d; asm("fma.rn.f32x2 %0,%1,%2,%3;":"=l"(d):"l"(a),"l"(b),"l"(c)); return d;
}
__device__ __forceinline__ u64 mul2(u64 a,u64 b){
    u64 d; asm("mul.rn.f32x2 %0,%1,%2;":"=l"(d):"l"(a),"l"(b)); return d;
}

// separable Gaussian weights (size 7, sigma 1.5); wz(k)=0 outside [0,6]
#define W0f 0.0366328f
#define W1f 0.1112808f
#define W2f 0.2167453f
#define W3f 0.2706821f
__device__ __forceinline__ float wz(int k){
    if (k < 0 || k > 6) return 0.f;
    return (k==0||k==6)?W0f:(k==1||k==5)?W1f:(k==2||k==4)?W2f:W3f;
}
__device__ __forceinline__ u64 wpz(int a,int b){   // packed weights; folds to constant
    return ((u64)__float_as_uint(wz(b))<<32) | (u64)__float_as_uint(wz(a));
}

#define CP_ASYNC16(dst, src) asm volatile("cp.async.cg.shared.global [%0], [%1], 16;" :: "r"(dst), "l"(src))
#define CP_COMMIT() asm volatile("cp.async.commit_group;")
#define CP_WAIT0()  asm volatile("cp.async.wait_group 0;")

__device__ double g_ssim_acc;   // zero-initialized; reset by last block each launch
__device__ int    g_done;

// x-direction conv of one (row, 4-col) task. Two packed fields:
//   t01 = conv_x(x, y)    tsp = conv_x(x^2 + y^2,  x*y)
__device__ __forceinline__ void xconv_task(char* SM, unsigned rawOffA, unsigned rawOffB,
                                           unsigned tabOff, int row, int xc0){
    const float* pa = (const float*)(SM + rawOffA) + row*SAW + xc0;
    const float* pb = (const float*)(SM + rawOffB) + row*SAW + xc0;
    float a[10], b[10];
    {
        float4 u = *(const float4*)pa;
        float4 v = *(const float4*)(pa+4);
        float2 w = *(const float2*)(pa+8);
        a[0]=u.x;a[1]=u.y;a[2]=u.z;a[3]=u.w;a[4]=v.x;a[5]=v.y;a[6]=v.z;a[7]=v.w;a[8]=w.x;a[9]=w.y;
    }
    {
        float4 u = *(const float4*)pb;
        float4 v = *(const float4*)(pb+4);
        float2 w = *(const float2*)(pb+8);
        b[0]=u.x;b[1]=u.y;b[2]=u.z;b[3]=u.w;b[4]=v.x;b[5]=v.y;b[6]=v.z;b[7]=v.w;b[8]=w.x;b[9]=w.y;
    }
    u64 a01[4], asp[4];
    #pragma unroll
    for (int m=0;m<10;m++){
        u64 pab = pack2(a[m], b[m]);
        float s = fmaf(b[m], b[m], a[m]*a[m]);
        float p = a[m]*b[m];
        u64 psp = pack2(s, p);
        #pragma unroll
        for (int c=0;c<4;c++){
            int k = m-c;
            if (k == 0){ a01[c]=mul2(wpz(0,0),pab); asp[c]=mul2(wpz(0,0),psp); }
            else if (k > 0 && k <= 6){ a01[c]=fma2(wpz(k,k),pab,a01[c]); asp[c]=fma2(wpz(k,k),psp,asp[c]); }
        }
    }
    ulonglong2* tab = (ulonglong2*)(SM + tabOff) + row*TABW + xc0;
    #pragma unroll
    for (int c=0;c<4;c++){
        ulonglong2 s; s.x = a01[c]; s.y = asp[c];
        tab[c] = s;
    }
}

// y-direction conv, 2 adjacent output rows, from one x-conved slice buffer
__device__ __forceinline__ void ystage(const char* SM, unsigned tabOff,
                                       int r0, int txi,
                                       u64& oa01, u64& oasp, u64& ob01, u64& obsp){
    const ulonglong2* tab = (const ulonglong2*)(SM + tabOff);
    #pragma unroll
    for (int j = 0; j < 8; ++j){
        ulonglong2 f = tab[(r0 + j)*TABW + txi];
        if (j == 0){
            oa01 = mul2(wpz(0,0), f.x);
            oasp = mul2(wpz(0,0), f.y);
        } else {
            if (j < 7){
                oa01 = fma2(wpz(j,j), f.x, oa01);
                oasp = fma2(wpz(j,j), f.y, oasp);
            }
            if (j == 1){
                ob01 = mul2(wpz(0,0), f.x);
                obsp = mul2(wpz(0,0), f.y);
            } else {
                ob01 = fma2(wpz(j-1,j-1), f.x, ob01);
                obsp = fma2(wpz(j-1,j-1), f.y, obsp);
            }
        }
    }
}

// z-conv + SSIM for one output row; B = (sy+1)%7 (oldest ring slot); folds after unroll
__device__ __forceinline__ void zssim_row(const u64* R01, const u64* Rsp, int B,
                                          bool v, float& acc){
    const float c1c = 1e-4f, c2c = 9e-4f;
    u64 m01 = mul2(wpz(0,0), R01[B % 7]);
    u64 msp = mul2(wpz(0,0), Rsp[B % 7]);
    #pragma unroll
    for (int k = 1; k < 7; ++k){
        m01 = fma2(wpz(k,k), R01[(B + k) % 7], m01);
        msp = fma2(wpz(k,k), Rsp[(B + k) % 7], msp);
    }
    float mu1,mu2,S,P;
    unpack2(m01, mu1, mu2);
    unpack2(msp, S, P);
    float m1s=mu1*mu1, m2s=mu2*mu2, mm=mu1*mu2;
    float num = (2.f*mm + c1c) * (2.f*(P - mm) + c2c);
    float den = (m1s + m2s + c1c) * ((S - m1s - m2s) + c2c);
    if (v) acc += __fdividef(num, den);
}

__global__ __launch_bounds__(NT,2)
void ssim_main_kernel(const float* __restrict__ X, const float* __restrict__ Y,
                      float* __restrict__ out){
    extern __shared__ char SM[];
    __shared__ float red[NT/32];

    const int t   = threadIdx.x;
    const int txi = t & 15;
    const int q   = t >> 4;

    const int gx0   = blockIdx.x * TX;
    const int gy0   = blockIdx.y * TY;
    const int batch = blockIdx.z >> 1;
    const int chunk = blockIdx.z & 1;

    const float* xb = X + (size_t)batch*PLANE*D + (size_t)(chunk*93)*PLANE;
    const float* yb = Y + (size_t)batch*PLANE*D + (size_t)(chunk*93)*PLANE;

    // ---- cp.async chunk assignment: 2 arrays x 38 rows x 6 chunks = 456 ----
    const float* p1; const float* p2;
    unsigned s1, s2; const bool have2 = (t < 200);
    {
        int cid1 = t;
        int c1   = (cid1 < 228) ? cid1 : cid1 - 228;
        int r1_  = c1/6, ck1 = c1 - 6*r1_;
        int gy1  = min(gy0 + r1_, D-1);
        int gxc1 = gx0 + ck1*4; if (gxc1 + 3 >= D) gxc1 = gx0;
        p1 = ((cid1 < 228) ? xb : yb) + gy1*D + gxc1;
        s1 = (unsigned)__cvta_generic_to_shared(
                 SM + ((cid1 < 228) ? OFF_A : OFF_B) + (unsigned)(r1_*(SAW*4) + ck1*16));
        int cid2 = t + 256;
        int c2   = cid2 - 228;                 // always array b
        int r2_  = c2/6, ck2 = c2 - 6*r2_;
        int gy2  = min(gy0 + r2_, D-1);
        int gxc2 = gx0 + ck2*4; if (gxc2 + 3 >= D) gxc2 = gx0;
        p2 = yb + gy2*D + gxc2;
        s2 = (unsigned)__cvta_generic_to_shared(
                 SM + OFF_B + (unsigned)(r2_*(SAW*4) + ck2*16));
    }

    // x-conv: 152 tasks (38 rows x 4 col-chunks), threads 0..151
    const bool xact = (t < 152);
    const int  xrow = t >> 2;
    const int  xc0  = (t & 3) * 4;

    // per-thread z rings (2 output rows x 2 packed fields)
    u64 Ra01[7], Rasp[7], Rb01[7], Rbsp[7];

    const int  r0 = 2*q;
    const bool okx = (gx0 + txi) < OUTD;
    const bool v0  = okx && (gy0 + r0 < OUTD);
    const bool v1  = okx && (gy0 + r0 + 1 < OUTD);

    float acc = 0.f;

    // ---- prologue: slices 0,1 into raw buffers 0,1 (one group) ----
    CP_ASYNC16(s1, p1); if (have2) CP_ASYNC16(s2, p2);
    CP_ASYNC16(s1 + RAW_BUF, p1 + PLANE); if (have2) CP_ASYNC16(s2 + RAW_BUF, p2 + PLANE);
    CP_COMMIT();
    p1 += 2*PLANE; p2 += 2*PLANE;

    unsigned rawRd = 0;    // byte off of raw buffer pair holding slices (2ip, 2ip+1)
    unsigned tabWr = 0;    // byte off of tab buffer pair for x-conv writes

    // pair-iterations ip = 0..50: x-conv slices (2ip,2ip+1), y/z slices (2ip-2,2ip-1)
    for (int pb = 0; pb <= 50; pb += 7){
        #pragma unroll
        for (int pp = 0; pp < 7; ++pp){
            const int ip = pb + pp;
            if (ip > 50) break;

            CP_WAIT0();
            __syncthreads();

            // prefetch slices 2ip+2, 2ip+3 into the opposite raw buffer pair
            {
                unsigned rawW = rawRd ^ (2u*RAW_BUF);
                if (ip <= 48){ CP_ASYNC16(s1 + rawW, p1); if (have2) CP_ASYNC16(s2 + rawW, p2); }
                if (ip <= 47){ CP_ASYNC16(s1 + rawW + RAW_BUF, p1 + PLANE);
                               if (have2) CP_ASYNC16(s2 + rawW + RAW_BUF, p2 + PLANE); }
                CP_COMMIT();
                p1 += 2*PLANE; p2 += 2*PLANE;
            }

            // ---- x-conv of slices 2ip, 2ip+1 ----
            if (xact){
                if (ip <= 49)
                    xconv_task(SM, OFF_A + rawRd, OFF_B + rawRd,
                               OFF_TAB + tabWr, xrow, xc0);
                if (ip <= 48)
                    xconv_task(SM, OFF_A + rawRd + RAW_BUF, OFF_B + rawRd + RAW_BUF,
                               OFF_TAB + tabWr + TAB_BUF, xrow, xc0);
            }

            // ---- y/z/SSIM for sy0 = 2ip-2, sy1 = 2ip-1 ----
            if (ip >= 1){
                const unsigned tabRd = tabWr ^ (2u*TAB_BUF);
                const int I0 = (2*pp + 5) % 7;   // sy0 % 7
                const int I1 = (2*pp + 6) % 7;   // sy1 % 7
                const int B0 = (2*pp + 6) % 7;   // (sy0+1) % 7
                const int B1 = (2*pp)     % 7;   // (sy1+1) % 7

                // sy0
                {
                    u64 oa01, oasp, ob01, obsp;
                    ystage(SM, OFF_TAB + tabRd, r0, txi, oa01, oasp, ob01, obsp);
                    Ra01[I0]=oa01; Rasp[I0]=oasp; Rb01[I0]=ob01; Rbsp[I0]=obsp;
                    if (ip >= 4){
                        zssim_row(Ra01, Rasp, B0, v0, acc);
                        zssim_row(Rb01, Rbsp, B0, v1, acc);
                    }
                }
                // sy1 (after zssim(sy0): slot I1 still holds sy0-6 until here)
                if (ip <= 49){
                    u64 oa01, oasp, ob01, obsp;
                    ystage(SM, OFF_TAB + tabRd + TAB_BUF, r0, txi, oa01, oasp, ob01, obsp);
                    Ra01[I1]=oa01; Rasp[I1]=oasp; Rb01[I1]=ob01; Rbsp[I1]=obsp;
                    if (ip >= 4){
                        zssim_row(Ra01, Rasp, B1, v0, acc);
                        zssim_row(Rb01, Rbsp, B1, v1, acc);
                    }
                }
            }

            rawRd ^= 2u*RAW_BUF;
            tabWr ^= 2u*TAB_BUF;
        }
    }

    // ---- reduction + fused finalize (last block writes out and resets) ----
    #pragma unroll
    for (int o = 16; o > 0; o >>= 1)
        acc += __shfl_xor_sync(0xffffffffu, acc, o);
    if ((t & 31) == 0) red[t >> 5] = acc;
    __syncthreads();
    if (t < 32){
        float v = (t < NT/32) ? red[t] : 0.f;
        #pragma unroll
        for (int o = 16; o > 0; o >>= 1)
            v += __shfl_xor_sync(0xffffffffu, v, o);
        if (t == 0){
            atomicAdd(&g_ssim_acc, (double)v);
            __threadfence();
            int old = atomicAdd(&g_done, 1);
            if (old == NBLOCKS - 1){
                __threadfence();
                double total = *((volatile double*)&g_ssim_acc);
                out[0] = (float)(total / 12869712.0);   // 2 * 186^3
                g_ssim_acc = 0.0;                        // reset for next replay
                g_done = 0;
            }
        }
    }
}

extern "C" void kernel_launch(void* const* d_in, const int* in_sizes, int n_in,
                              void* d_out, int out_size){
    const float* x = (const float*)d_in[0];
    const float* y = (const float*)d_in[1];
    float* out = (float*)d_out;

    cudaFuncSetAttribute(ssim_main_kernel,
                         cudaFuncAttributeMaxDynamicSharedMemorySize, SMEM_TOTAL);

    dim3 grid(12, 6, 4);   // 192/16 x-tiles, 192/32 y-tiles, 2 batches * 2 z-chunks
    ssim_main_kernel<<<grid, NT, SMEM_TOTAL>>>(x, y, out);
}